// round 2
// baseline (speedup 1.0000x reference)
#include <cuda_runtime.h>
#include <cuda_fp16.h>
#include <cstdint>

// ---------------------------------------------------------------------------
// out[b,s,o] = sum_i x[b,s,i] * (nf4[codes][o,i] * scale[o]) + bias[o]
// M = 8192, N = 4096, K = 4096, fp32 in/out.
// Toolchain compiles at plain sm_103 (no 'a' feature set) -> tcgen05 is
// unavailable. Use mma.sync.m16n8k16 (HMMA) + ldmatrix + cp.async pipeline.
// fp16 operands, fp32 accumulation (bf16 operands would miss rel_err<1e-3).
// ---------------------------------------------------------------------------

static constexpr int M_TOTAL = 8192;
static constexpr int N_TOTAL = 4096;
static constexpr int K_TOTAL = 4096;

static constexpr int BM = 128;
static constexpr int BN = 128;
static constexpr int BK = 64;            // 64 halfs = 128 bytes per row (SW128)
static constexpr int STAGES = 3;
static constexpr int KITERS = K_TOTAL / BK;  // 64

static constexpr int A_BYTES = BM * 128;     // 16 KB per stage
static constexpr int B_BYTES = BN * 128;     // 16 KB per stage
static constexpr int STAGE_BYTES = A_BYTES + B_BYTES;          // 32 KB
static constexpr int SMEM_BYTES = STAGES * STAGE_BYTES;        // 96 KB

// scratch (static __device__ arrays: the sanctioned no-alloc workaround)
__device__ __align__(1024) __half g_Wh[(size_t)N_TOTAL * K_TOTAL];  // 32 MB
__device__ __align__(1024) __half g_Xh[(size_t)M_TOTAL * K_TOTAL];  // 64 MB

__constant__ float c_nf4[16] = {
    -1.0f, -0.6961928f, -0.52507305f, -0.3949175f, -0.28444138f, -0.18477343f,
    -0.09105004f, 0.0f, 0.0795803f, 0.1609302f, 0.2461123f, 0.33791524f,
    0.44070983f, 0.562617f, 0.72295684f, 1.0f};

// ------------------------------- helpers -----------------------------------

__device__ __forceinline__ uint32_t smem_u32(const void* p) {
  uint32_t a;
  asm("{ .reg .u64 t; cvta.to.shared.u64 t, %1; cvt.u32.u64 %0, t; }"
      : "=r"(a) : "l"(p));
  return a;
}

#define SWZ128(b) ((b) ^ (((b) >> 3) & 0x70))

#define CP_ASYNC16(dst, gsrc)                                          \
  asm volatile("cp.async.cg.shared.global [%0], [%1], 16;" ::"r"(dst), \
               "l"(gsrc)                                               \
               : "memory")
#define CP_COMMIT() asm volatile("cp.async.commit_group;" ::: "memory")
#define CP_WAIT1() asm volatile("cp.async.wait_group 1;" ::: "memory")

#define LDSM_X4(r0, r1, r2, r3, addr)                                     \
  asm volatile(                                                           \
      "ldmatrix.sync.aligned.m8n8.x4.shared.b16 {%0,%1,%2,%3}, [%4];"     \
      : "=r"(r0), "=r"(r1), "=r"(r2), "=r"(r3)                            \
      : "r"(addr))

#define MMA16816(c0, c1, c2, c3, a0, a1, a2, a3, b0, b1)                  \
  asm volatile(                                                           \
      "mma.sync.aligned.m16n8k16.row.col.f32.f16.f16.f32 "                \
      "{%0,%1,%2,%3}, {%4,%5,%6,%7}, {%8,%9}, {%0,%1,%2,%3};"             \
      : "+f"(c0), "+f"(c1), "+f"(c2), "+f"(c3)                            \
      : "r"(a0), "r"(a1), "r"(a2), "r"(a3), "r"(b0), "r"(b1))

// ------------------------------ pre-kernels --------------------------------

__global__ void k_dequant(const int* __restrict__ codes,
                          const float* __restrict__ scale) {
  __shared__ float cb[16];
  if (threadIdx.x < 16) cb[threadIdx.x] = c_nf4[threadIdx.x];
  __syncthreads();
  int idx = blockIdx.x * blockDim.x + threadIdx.x;  // 0 .. 8388607
  int e = codes[idx];
  float s = scale[idx >> 11];  // o = (2*idx) / 4096
  __half2 h = __floats2half2_rn(cb[e & 15] * s, cb[(e >> 4) & 15] * s);
  reinterpret_cast<__half2*>(g_Wh)[idx] = h;
}

__global__ void k_convert(const float4* __restrict__ x4) {
  int i = blockIdx.x * blockDim.x + threadIdx.x;  // 0 .. 8388607
  float4 v = x4[i];
  __half2 a = __floats2half2_rn(v.x, v.y);
  __half2 b = __floats2half2_rn(v.z, v.w);
  uint2 u;
  u.x = reinterpret_cast<uint32_t&>(a);
  u.y = reinterpret_cast<uint32_t&>(b);
  reinterpret_cast<uint2*>(g_Xh)[i] = u;
}

// ------------------------------- GEMM kernel -------------------------------
// 256 threads = 8 warps in 4(m) x 2(n) grid. Warp tile 32x64.
// Per k-step of 16: A = 2x ldmatrix.x4, B = 4x ldmatrix.x4, 16 HMMA.

__global__ __launch_bounds__(256, 2) void k_gemm(const float* __restrict__ bias,
                                                 float* __restrict__ out) {
  extern __shared__ char smem[];
  const uint32_t sb = smem_u32(smem);
  const int tid = threadIdx.x;
  const int wid = tid >> 5;
  const int lid = tid & 31;
  const int wm = wid & 3;   // 0..3 -> 32-row slice
  const int wn = wid >> 2;  // 0..1 -> 64-col slice
  const int n0 = blockIdx.x * BN;
  const int m0 = blockIdx.y * BM;

  float c[2][8][4];
#pragma unroll
  for (int i = 0; i < 2; ++i)
#pragma unroll
    for (int j = 0; j < 8; ++j)
#pragma unroll
      for (int v = 0; v < 4; ++v) c[i][j][v] = 0.f;

  // ------- tile loader: 8x 16B chunks per thread (4 A + 4 B) -------
  auto load_stage = [&](int s, int kt) {
    const uint32_t stage = sb + s * STAGE_BYTES;
#pragma unroll
    for (int i = 0; i < 4; ++i) {
      const int ca = tid + 256 * i;       // A chunk id 0..1023
      const int row = ca >> 3;
      const int u = ca & 7;
      const __half* src =
          g_Xh + ((size_t)(m0 + row) * K_TOTAL + kt * BK + u * 8);
      CP_ASYNC16(stage + SWZ128((uint32_t)(row * 128 + u * 16)),
                 (const void*)src);
    }
#pragma unroll
    for (int i = 0; i < 4; ++i) {
      const int cbk = tid + 256 * i;      // B chunk id 0..1023
      const int row = cbk >> 3;
      const int u = cbk & 7;
      const __half* src =
          g_Wh + ((size_t)(n0 + row) * K_TOTAL + kt * BK + u * 8);
      CP_ASYNC16(stage + A_BYTES + SWZ128((uint32_t)(row * 128 + u * 16)),
                 (const void*)src);
    }
  };

  // ------- prologue: stages 0,1 in flight -------
  load_stage(0, 0);
  CP_COMMIT();
  load_stage(1, 1);
  CP_COMMIT();

  // ldmatrix lane addressing (constant across iters except stage base)
  const int a_row = wm * 32 + (lid & 15);          // + mt*16
  const int a_kb = (lid >> 4) * 16;                // + ks*32
  const int b_row = wn * 64 + ((lid >> 4) * 8) + (lid & 7);  // + p*16
  const int b_kb = ((lid >> 3) & 1) * 16;          // + ks*32

  for (int kt = 0; kt < KITERS; ++kt) {
    CP_WAIT1();
    __syncthreads();
    if (kt + 2 < KITERS) load_stage((kt + 2) % STAGES, kt + 2);
    CP_COMMIT();

    const int s = kt % STAGES;
    const uint32_t aBase = sb + s * STAGE_BYTES;
    const uint32_t bBase = aBase + A_BYTES;
#pragma unroll
    for (int ks = 0; ks < 4; ++ks) {
      uint32_t a[2][4];
#pragma unroll
      for (int mt = 0; mt < 2; ++mt) {
        uint32_t off = (uint32_t)((a_row + mt * 16) * 128 + ks * 32 + a_kb);
        LDSM_X4(a[mt][0], a[mt][1], a[mt][2], a[mt][3], aBase + SWZ128(off));
      }
      uint32_t b[4][4];
#pragma unroll
      for (int p = 0; p < 4; ++p) {
        uint32_t off = (uint32_t)((b_row + p * 16) * 128 + ks * 32 + b_kb);
        LDSM_X4(b[p][0], b[p][1], b[p][2], b[p][3], bBase + SWZ128(off));
      }
#pragma unroll
      for (int mt = 0; mt < 2; ++mt)
#pragma unroll
        for (int nt = 0; nt < 8; ++nt) {
          MMA16816(c[mt][nt][0], c[mt][nt][1], c[mt][nt][2], c[mt][nt][3],
                   a[mt][0], a[mt][1], a[mt][2], a[mt][3],
                   b[nt >> 1][(nt & 1) * 2], b[nt >> 1][(nt & 1) * 2 + 1]);
        }
    }
  }

  // ------------------------------ epilogue ---------------------------------
  const int mrow = m0 + wm * 32 + (lid >> 2);
  const int ncol = n0 + wn * 64 + (lid & 3) * 2;
  float2 bias2[8];
#pragma unroll
  for (int nt = 0; nt < 8; ++nt)
    bias2[nt] = *reinterpret_cast<const float2*>(bias + ncol + nt * 8);

#pragma unroll
  for (int mt = 0; mt < 2; ++mt) {
#pragma unroll
    for (int nt = 0; nt < 8; ++nt) {
      float* p0 = out + (size_t)(mrow + mt * 16) * N_TOTAL + ncol + nt * 8;
      float* p1 = p0 + 8 * N_TOTAL;
      float2 v0 = {c[mt][nt][0] + bias2[nt].x, c[mt][nt][1] + bias2[nt].y};
      float2 v1 = {c[mt][nt][2] + bias2[nt].x, c[mt][nt][3] + bias2[nt].y};
      *reinterpret_cast<float2*>(p0) = v0;
      *reinterpret_cast<float2*>(p1) = v1;
    }
  }
}

// ------------------------------- launcher ----------------------------------

extern "C" void kernel_launch(void* const* d_in, const int* in_sizes, int n_in,
                              void* d_out, int out_size) {
  const float* x = (const float*)d_in[0];
  const int* codes = (const int*)d_in[1];
  const float* scale = (const float*)d_in[2];
  const float* bias = (const float*)d_in[3];
  float* out = (float*)d_out;

  k_dequant<<<(N_TOTAL * K_TOTAL / 2) / 256, 256>>>(codes, scale);
  k_convert<<<(M_TOTAL * K_TOTAL / 4) / 256, 256>>>((const float4*)x);

  cudaFuncSetAttribute(k_gemm, cudaFuncAttributeMaxDynamicSharedMemorySize,
                       SMEM_BYTES);
  dim3 grid(N_TOTAL / BN, M_TOTAL / BM);  // (32, 64)
  k_gemm<<<grid, 256, SMEM_BYTES>>>(bias, out);
}